// round 8
// baseline (speedup 1.0000x reference)
#include <cuda_runtime.h>

#define NEG (-1e30f)

// dims
#define BB   8
#define NN   196
#define DD   128
#define DFF  256
#define PD   256
#define MM   (BB*NN)   // 1568
#define CC   1000

// -------- scratch (device globals; no allocation allowed) --------
__device__ __align__(128) float g_h[MM * DD];
__device__ __align__(128) float g_q[MM * DD];
__device__ __align__(128) float g_k[MM * DD];
__device__ __align__(128) float g_v[MM * DD];
__device__ __align__(128) float g_t[MM * DFF];
__device__ __align__(128) float g_mx[MM];

// -------- Blackwell packed helpers --------
__device__ __forceinline__ float fmax3(float a, float b, float c) {
    float d;
    asm("max.f32 %0, %1, %2, %3;" : "=f"(d) : "f"(a), "f"(b), "f"(c));
    return d;
}
__device__ __forceinline__ unsigned long long addx2(unsigned long long a,
                                                    unsigned long long b) {
    unsigned long long r;
    asm("add.rn.f32x2 %0, %1, %2;" : "=l"(r) : "l"(a), "l"(b));
    return r;
}
__device__ __forceinline__ void unpk(float& lo, float& hi, unsigned long long v) {
    asm("mov.b64 {%0, %1}, %2;" : "=f"(lo), "=f"(hi) : "l"(v));
}
__device__ __forceinline__ unsigned long long pk(float lo, float hi) {
    unsigned long long v;
    asm("mov.b64 %0, {%1, %2};" : "=l"(v) : "f"(lo), "f"(hi));
    return v;
}

// ---------------------------------------------------------------
// X-tile loaders (stage ROWS x 64 k-chunk into shared, t < ROWS*16)
// ---------------------------------------------------------------
struct XRow {
    const float* X; int m0; int ld;
    __device__ __forceinline__ void operator()(float (*sx)[68], int k0, int t) const {
        int row = t >> 4, kp = (t & 15) * 4;
        *(float4*)&sx[row][kp] = *(const float4*)&X[(m0 + row) * ld + k0 + kp];
    }
};
// patchify-on-the-fly: x is (8,224,224); row m -> (b,n); k index j -> (py,px)
struct XPatch {
    const float* x; int m0;
    __device__ __forceinline__ void operator()(float (*sx)[68], int k0, int t) const {
        int row = t >> 4, kp = (t & 15) * 4;
        int m = m0 + row;
        int b = m / NN, n = m % NN;
        int gy = n / 14, gx = n % 14;
        int j = k0 + kp;
        int py = j >> 4, px = j & 15;
        *(float4*)&sx[row][kp] =
            *(const float4*)&x[(b * 224 + gy * 16 + py) * 224 + gx * 16 + px];
    }
};

// ---------------------------------------------------------------
// K-split tropical GEMM core. Block = 256 threads: col c = t&127,
// K-group g = t>>7 handles kk in [g*32, g*32+32) of each 64-chunk.
// Inner loop: packed f32x2 adds + 3-input max (FMNMX3).
// ---------------------------------------------------------------
template<int ROWS, int K, class XL>
__device__ __forceinline__ void trop_core(const XL& xl, const float* __restrict__ W,
                                          float acc[ROWS],
                                          float (*sx)[68], float (*sw)[68])
{
    int t = threadIdx.x;
    int c = t & 127, kbase = (t >> 7) * 32;
#pragma unroll
    for (int m = 0; m < ROWS; m++) acc[m] = NEG;

    for (int k0 = 0; k0 < K; k0 += 64) {
        if (t < ROWS * 16) xl(sx, k0, t);
#pragma unroll
        for (int p = 0; p < 8; p++) {        // 128 rows x 16 float4 / 256 thr
            int l = p * 256 + t;
            int i = l >> 4, kp = (l & 15) * 4;
            *(float4*)&sw[i][kp] = *(const float4*)&W[i * K + k0 + kp];
        }
        __syncthreads();
#pragma unroll
        for (int kk = 0; kk < 32; kk += 4) {
            ulonglong2 wv = *(const ulonglong2*)&sw[c][kbase + kk];
#pragma unroll
            for (int m = 0; m < ROWS; m++) {
                ulonglong2 xv = *(const ulonglong2*)&sx[m][kbase + kk]; // broadcast
                unsigned long long s01 = addx2(xv.x, wv.x);
                unsigned long long s23 = addx2(xv.y, wv.y);
                float s0, s1, s2, s3;
                unpk(s0, s1, s01);
                unpk(s2, s3, s23);
                acc[m] = fmax3(acc[m], s0, s1);
                acc[m] = fmax3(acc[m], s2, s3);
            }
        }
        __syncthreads();
    }
}

// combine the two K-groups: after this, group 0 (t<128) holds the result
template<int ROWS>
__device__ __forceinline__ void combine(float acc[ROWS], float (*sc)[128]) {
    int t = threadIdx.x, c = t & 127;
    if (t >= 128) {
#pragma unroll
        for (int m = 0; m < ROWS; m++) sc[m][c] = acc[m];
    }
    __syncthreads();
    if (t < 128) {
#pragma unroll
        for (int m = 0; m < ROWS; m++) acc[m] = fmaxf(acc[m], sc[m][c]);
    }
}

// ---------------------------------------------------------------
// embed: h = trop_mm(patchify(x), embed_W) + pos ; g_mx = rowmax(h)
// grid 784, block 256 (2 rows/block)
// ---------------------------------------------------------------
__global__ void __launch_bounds__(256) embed_kernel(
        const float* __restrict__ x, const float* __restrict__ W,
        const float* __restrict__ pos) {
    __shared__ float sx[2][68];
    __shared__ float sw[128][68];
    __shared__ float sc[2][128];
    __shared__ float red[4][2];
    int t = threadIdx.x, m0 = blockIdx.x * 2;
    float acc[2];
    XPatch xl{x, m0};
    trop_core<2, PD>(xl, W, acc, sx, sw);
    combine<2>(acc, sc);
    if (t < 128) {
        int warp = t >> 5, lane = t & 31;
#pragma unroll
        for (int m = 0; m < 2; m++) {
            acc[m] += pos[((m0 + m) % NN) * DD + t];
            g_h[(m0 + m) * DD + t] = acc[m];
            float v = acc[m];
#pragma unroll
            for (int o = 16; o; o >>= 1) v = fmaxf(v, __shfl_xor_sync(~0u, v, o));
            if (lane == 0) red[warp][m] = v;
        }
    }
    __syncthreads();
    if (t < 2)
        g_mx[m0 + t] = fmax3(fmaxf(red[0][t], red[1][t]), red[2][t], red[3][t]);
}

// ---------------------------------------------------------------
// qkv: {q,k,v} = trop_mm(h, W) - mx
// grid (392,3), block 256 (4 rows/block)
// ---------------------------------------------------------------
__global__ void __launch_bounds__(256) qkv_kernel(
        const float* __restrict__ qW, const float* __restrict__ kW,
        const float* __restrict__ vW) {
    __shared__ float sx[4][68];
    __shared__ float sw[128][68];
    __shared__ float sc[4][128];
    int t = threadIdx.x, m0 = blockIdx.x * 4;
    const float* W = (blockIdx.y == 0) ? qW : (blockIdx.y == 1) ? kW : vW;
    float* O = (blockIdx.y == 0) ? g_q : (blockIdx.y == 1) ? g_k : g_v;
    float acc[4];
    XRow xl{g_h, m0, DD};
    trop_core<4, DD>(xl, W, acc, sx, sw);
    combine<4>(acc, sc);
    if (t < 128) {
#pragma unroll
        for (int m = 0; m < 4; m++)
            O[(m0 + m) * DD + t] = acc[m] - g_mx[m0 + m];
    }
}

// ---------------------------------------------------------------
// fused attention + residual + rowmax epilogue
// grid (25, 8), block 256 = 8 i-rows x 32 lanes (4 d each)
// ---------------------------------------------------------------
__global__ void attn_kernel() {
    __shared__ float ks[8][128];
    __shared__ float vs[8][128];
    int t = threadIdx.x;
    int b = blockIdx.y;
    int il = t >> 5, lane = t & 31;
    int d0 = lane * 4;
    int i = blockIdx.x * 8 + il;
    bool iv = (i < NN);

    const float* qp = g_q + (b * NN + (iv ? i : 0)) * DD + d0;
    float q0 = iv ? qp[0] : NEG, q1 = iv ? qp[1] : NEG;
    float q2 = iv ? qp[2] : NEG, q3 = iv ? qp[3] : NEG;
    unsigned long long Q01 = pk(q0, q1), Q23 = pk(q2, q3);
    float U0 = NEG, U1 = NEG, U2 = NEG, U3 = NEG;

    for (int j0 = 0; j0 < NN; j0 += 8) {
        int j = j0 + il;
        if (j < NN) {
            const float* kp_ = g_k + (b * NN + j) * DD + d0;
            const float* vp_ = g_v + (b * NN + j) * DD + d0;
            *(float4*)&ks[il][d0] = *(const float4*)&kp_[0];
            *(float4*)&vs[il][d0] = *(const float4*)&vp_[0];
        } else {
            float4 nv = make_float4(NEG, NEG, NEG, NEG);
            *(float4*)&ks[il][d0] = nv;
            *(float4*)&vs[il][d0] = nv;
        }
        __syncthreads();
#pragma unroll
        for (int jj = 0; jj < 8; jj++) {
            ulonglong2 kv = *(const ulonglong2*)&ks[jj][d0];
            float s0, s1, s2, s3;
            unpk(s0, s1, addx2(Q01, kv.x));
            unpk(s2, s3, addx2(Q23, kv.y));
            float s = fmaxf(fmax3(s0, s1, s2), s3);
#pragma unroll
            for (int o = 16; o; o >>= 1) s = fmaxf(s, __shfl_xor_sync(~0u, s, o));
            ulonglong2 vv = *(const ulonglong2*)&vs[jj][d0];
            unsigned long long S2 = pk(s, s);
            float a0, a1, a2, a3;
            unpk(a0, a1, addx2(S2, vv.x));
            unpk(a2, a3, addx2(S2, vv.y));
            U0 = fmaxf(U0, a0); U1 = fmaxf(U1, a1);
            U2 = fmaxf(U2, a2); U3 = fmaxf(U3, a3);
        }
        __syncthreads();
    }

    float um = fmax3(fmaxf(U0, U1), U2, U3);
#pragma unroll
    for (int o = 16; o; o >>= 1) um = fmaxf(um, __shfl_xor_sync(~0u, um, o));

    if (iv) {
        float* hp = g_h + (b * NN + i) * DD + d0;
        float h0 = fmaxf(hp[0], U0 - um), h1 = fmaxf(hp[1], U1 - um);
        float h2 = fmaxf(hp[2], U2 - um), h3 = fmaxf(hp[3], U3 - um);
        hp[0] = h0; hp[1] = h1; hp[2] = h2; hp[3] = h3;
        float v = fmax3(fmaxf(h0, h1), h2, h3);
#pragma unroll
        for (int o = 16; o; o >>= 1) v = fmaxf(v, __shfl_xor_sync(~0u, v, o));
        if (lane == 0) g_mx[b * NN + i] = v;
    }
}

// ---------------------------------------------------------------
// ff1: t = max(trop_mm(h, f1W) - mx, tau)
// grid (392, 2), block 256 (4 rows/block)
// ---------------------------------------------------------------
__global__ void __launch_bounds__(256) ff1_kernel(
        const float* __restrict__ W, const float* __restrict__ tau) {
    __shared__ float sx[4][68];
    __shared__ float sw[128][68];
    __shared__ float sc[4][128];
    int t = threadIdx.x, m0 = blockIdx.x * 4;
    float acc[4];
    XRow xl{g_h, m0, DD};
    trop_core<4, DD>(xl, W + blockIdx.y * 128 * DD, acc, sx, sw);
    combine<4>(acc, sc);
    if (t < 128) {
        float tv = tau[0];
#pragma unroll
        for (int m = 0; m < 4; m++)
            g_t[(m0 + m) * DFF + blockIdx.y * 128 + t] =
                fmaxf(acc[m] - g_mx[m0 + m], tv);
    }
}

// ---------------------------------------------------------------
// ff2: u = trop_mm(t, f2W); h = max(h, u - rowmax(u)); g_mx = rowmax(h)
// grid 784, block 256 (2 rows/block)
// ---------------------------------------------------------------
__global__ void __launch_bounds__(256) ff2_kernel(const float* __restrict__ W) {
    __shared__ float sx[2][68];
    __shared__ float sw[128][68];
    __shared__ float sc[2][128];
    __shared__ float red[4][2];
    int t = threadIdx.x, m0 = blockIdx.x * 2;
    float acc[2];
    XRow xl{g_t, m0, DFF};
    trop_core<2, DFF>(xl, W, acc, sx, sw);
    combine<2>(acc, sc);

    int warp = t >> 5, lane = t & 31;
    if (t < 128) {
#pragma unroll
        for (int m = 0; m < 2; m++) {
            float v = acc[m];
#pragma unroll
            for (int o = 16; o; o >>= 1) v = fmaxf(v, __shfl_xor_sync(~0u, v, o));
            if (lane == 0) red[warp][m] = v;
        }
    }
    __syncthreads();
    float hn[2];
    if (t < 128) {
#pragma unroll
        for (int m = 0; m < 2; m++) {
            float rm = fmax3(fmaxf(red[0][m], red[1][m]), red[2][m], red[3][m]);
            hn[m] = fmaxf(g_h[(m0 + m) * DD + t], acc[m] - rm);
            g_h[(m0 + m) * DD + t] = hn[m];
        }
    }
    __syncthreads();
    if (t < 128) {
#pragma unroll
        for (int m = 0; m < 2; m++) {
            float v = hn[m];
#pragma unroll
            for (int o = 16; o; o >>= 1) v = fmaxf(v, __shfl_xor_sync(~0u, v, o));
            if (lane == 0) red[warp][m] = v;
        }
    }
    __syncthreads();
    if (t < 2)
        g_mx[m0 + t] = fmax3(fmaxf(red[0][t], red[1][t]), red[2][t], red[3][t]);
}

// ---------------------------------------------------------------
// head with fused tropical global pool
// grid (8, 63), block 128 = 16 c-rows x 8 lanes (16 d each)
// ---------------------------------------------------------------
__global__ void head_kernel(const float* __restrict__ W, const float* __restrict__ ls,
                            float* __restrict__ out) {
    __shared__ float sp[128];
    int t = threadIdx.x, b = blockIdx.x;
    const float* hp = g_h + b * NN * DD + t;
    float v0 = NEG, v1 = NEG, v2 = NEG, v3 = NEG;
    for (int n = 0; n < NN; n += 4) {
        v0 = fmaxf(v0, hp[n * DD]);
        v1 = fmaxf(v1, hp[(n + 1) * DD]);
        v2 = fmaxf(v2, hp[(n + 2) * DD]);
        v3 = fmaxf(v3, hp[(n + 3) * DD]);
    }
    sp[t] = fmax3(fmaxf(v0, v1), v2, v3);
    __syncthreads();

    int c = blockIdx.y * 16 + (t >> 3);
    int dp = (t & 7) * 16;
    float acc = NEG;
    if (c < CC) {
        const float* w = W + c * DD + dp;
#pragma unroll
        for (int d = 0; d < 16; d += 4) {
            float4 wv = *(const float4*)&w[d];
            acc = fmax3(acc, fmaxf(sp[dp + d] + wv.x, sp[dp + d + 1] + wv.y),
                        fmaxf(sp[dp + d + 2] + wv.z, sp[dp + d + 3] + wv.w));
        }
    }
#pragma unroll
    for (int o = 4; o; o >>= 1) acc = fmaxf(acc, __shfl_xor_sync(~0u, acc, o));
    if ((t & 7) == 0 && c < CC) out[b * CC + c] = acc * ls[0];
}

// ---------------------------------------------------------------
extern "C" void kernel_launch(void* const* d_in, const int* in_sizes, int n_in,
                              void* d_out, int out_size) {
    const float* x      = (const float*)d_in[0];
    const float* embedW = (const float*)d_in[1];
    const float* pos    = (const float*)d_in[2];
    const float* qW[2]  = {(const float*)d_in[3],  (const float*)d_in[9]};
    const float* kW[2]  = {(const float*)d_in[4],  (const float*)d_in[10]};
    const float* vW[2]  = {(const float*)d_in[5],  (const float*)d_in[11]};
    const float* f1W[2] = {(const float*)d_in[6],  (const float*)d_in[12]};
    const float* f2W[2] = {(const float*)d_in[7],  (const float*)d_in[13]};
    const float* tau[2] = {(const float*)d_in[8],  (const float*)d_in[14]};
    const float* headW  = (const float*)d_in[15];
    const float* ls     = (const float*)d_in[16];
    float* out = (float*)d_out;

    embed_kernel<<<MM / 2, 256>>>(x, embedW, pos);

    for (int l = 0; l < 2; l++) {
        qkv_kernel<<<dim3(MM / 4, 3), 256>>>(qW[l], kW[l], vW[l]);
        attn_kernel<<<dim3(25, BB), 256>>>();
        ff1_kernel<<<dim3(MM / 4, 2), 256>>>(f1W[l], tau[l]);
        ff2_kernel<<<MM / 2, 256>>>(f2W[l]);
    }

    head_kernel<<<dim3(BB, 63), 128>>>(headW, ls, out);
}

// round 9
// speedup vs baseline: 1.2276x; 1.2276x over previous
#include <cuda_runtime.h>

#define NEG (-1e30f)

// dims
#define BB   8
#define NN   196
#define DD   128
#define DFF  256
#define PD   256
#define MM   (BB*NN)   // 1568
#define CC   1000

// -------- scratch (device globals; no allocation allowed) --------
__device__ __align__(128) float g_h[MM * DD];
__device__ __align__(128) float g_q[MM * DD];
__device__ __align__(128) float g_k[MM * DD];
__device__ __align__(128) float g_v[MM * DD];
__device__ __align__(128) float g_t[MM * DFF];
__device__ __align__(128) float g_mx[MM];

// -------- Blackwell packed helpers --------
__device__ __forceinline__ float fmax3(float a, float b, float c) {
    float d;
    asm("max.f32 %0, %1, %2, %3;" : "=f"(d) : "f"(a), "f"(b), "f"(c));
    return d;
}
__device__ __forceinline__ unsigned long long addx2(unsigned long long a,
                                                    unsigned long long b) {
    unsigned long long r;
    asm("add.rn.f32x2 %0, %1, %2;" : "=l"(r) : "l"(a), "l"(b));
    return r;
}
__device__ __forceinline__ void unpk(float& lo, float& hi, unsigned long long v) {
    asm("mov.b64 {%0, %1}, %2;" : "=f"(lo), "=f"(hi) : "l"(v));
}
__device__ __forceinline__ unsigned long long pk(float lo, float hi) {
    unsigned long long v;
    asm("mov.b64 %0, {%1, %2};" : "=l"(v) : "f"(lo), "f"(hi));
    return v;
}

// -------- cp.async helpers --------
__device__ __forceinline__ void cpa16(float* dst, const float* src) {
    unsigned a = (unsigned)__cvta_generic_to_shared(dst);
    asm volatile("cp.async.cg.shared.global [%0], [%1], 16;" :: "r"(a), "l"(src));
}
__device__ __forceinline__ void cpa_commit() {
    asm volatile("cp.async.commit_group;");
}
template<int N>
__device__ __forceinline__ void cpa_wait() {
    asm volatile("cp.async.wait_group %0;" :: "n"(N));
}

// ---------------------------------------------------------------
// X source-address providers (gmem pointer for a 16B piece)
// ---------------------------------------------------------------
struct XRow {
    const float* X; int m0; int ld;
    __device__ __forceinline__ const float* src(int k0, int row, int kp) const {
        return &X[(m0 + row) * ld + k0 + kp];
    }
};
// patchify-on-the-fly: x is (8,224,224); row m -> (b,n); k index j -> (py,px)
struct XPatch {
    const float* x; int m0;
    __device__ __forceinline__ const float* src(int k0, int row, int kp) const {
        int m = m0 + row;
        int b = m / NN, n = m % NN;
        int gy = n / 14, gx = n % 14;
        int j = k0 + kp;
        int py = j >> 4, px = j & 15;
        return &x[(b * 224 + gy * 16 + py) * 224 + gx * 16 + px];
    }
};

// ---------------------------------------------------------------
// K-split tropical GEMM core with cp.async double-buffered staging.
// Block = 256 threads: col c = t&127, K-group g = t>>7 handles
// kk in [g*32, g*32+32) of each 64-chunk.
// Dynamic smem layout: sw[2][128][68], sx[2][ROWS][68] (sc aliases later).
// ---------------------------------------------------------------
template<int ROWS, int K, class XL>
__device__ __forceinline__ void trop_core(const XL& xl, const float* __restrict__ W,
                                          float acc[ROWS], float* dyn)
{
    float (*sw)[128][68] = (float (*)[128][68])dyn;
    float (*sx)[ROWS][68] = (float (*)[ROWS][68])(dyn + 2 * 128 * 68);
    int t = threadIdx.x;
    int c = t & 127, kbase = (t >> 7) * 32;
#pragma unroll
    for (int m = 0; m < ROWS; m++) acc[m] = NEG;

    auto stage = [&](int buf, int k0) {
        if (t < ROWS * 16) {
            int row = t >> 4, kp = (t & 15) * 4;
            cpa16(&sx[buf][row][kp], xl.src(k0, row, kp));
        }
#pragma unroll
        for (int p = 0; p < 8; p++) {        // 128 rows x 16 float4 / 256 thr
            int l = p * 256 + t;
            int i = l >> 4, kp = (l & 15) * 4;
            cpa16(&sw[buf][i][kp], &W[i * K + k0 + kp]);
        }
        cpa_commit();
    };

    stage(0, 0);
#pragma unroll
    for (int ci = 0; ci < K / 64; ci++) {
        int buf = ci & 1;
        if (ci + 1 < K / 64) {               // prefetch next chunk, then wait
            stage(buf ^ 1, (ci + 1) * 64);   //   for current (1 grp in flight)
            cpa_wait<1>();
        } else {
            cpa_wait<0>();
        }
        __syncthreads();
#pragma unroll
        for (int kk = 0; kk < 32; kk += 4) {
            ulonglong2 wv = *(const ulonglong2*)&sw[buf][c][kbase + kk];
#pragma unroll
            for (int m = 0; m < ROWS; m++) {
                ulonglong2 xv = *(const ulonglong2*)&sx[buf][m][kbase + kk]; // bcast
                unsigned long long s01 = addx2(xv.x, wv.x);
                unsigned long long s23 = addx2(xv.y, wv.y);
                float s0, s1, s2, s3;
                unpk(s0, s1, s01);
                unpk(s2, s3, s23);
                acc[m] = fmax3(acc[m], s0, s1);
                acc[m] = fmax3(acc[m], s2, s3);
            }
        }
        __syncthreads();
    }
}

// combine the two K-groups: after this, group 0 (t<128) holds the result.
// sc may alias the dynamic buffer (all smem reads of the core are done).
template<int ROWS>
__device__ __forceinline__ void combine(float acc[ROWS], float (*sc)[128]) {
    int t = threadIdx.x, c = t & 127;
    if (t >= 128) {
#pragma unroll
        for (int m = 0; m < ROWS; m++) sc[m][c] = acc[m];
    }
    __syncthreads();
    if (t < 128) {
#pragma unroll
        for (int m = 0; m < ROWS; m++) acc[m] = fmaxf(acc[m], sc[m][c]);
    }
}

#define SMEM8 ((2 * 128 * 68 + 2 * 8 * 68) * 4)
#define SMEM4 ((2 * 128 * 68 + 2 * 4 * 68) * 4)

// ---------------------------------------------------------------
// embed: h = trop_mm(patchify(x), embed_W) + pos ; g_mx = rowmax(h)
// grid 392, block 256 (4 rows/block)
// ---------------------------------------------------------------
__global__ void __launch_bounds__(256) embed_kernel(
        const float* __restrict__ x, const float* __restrict__ W,
        const float* __restrict__ pos) {
    extern __shared__ float dyn[];
    __shared__ float red[4][4];
    int t = threadIdx.x, m0 = blockIdx.x * 4;
    float acc[4];
    XPatch xl{x, m0};
    trop_core<4, PD>(xl, W, acc, dyn);
    combine<4>(acc, (float (*)[128])dyn);
    if (t < 128) {
        int warp = t >> 5, lane = t & 31;
#pragma unroll
        for (int m = 0; m < 4; m++) {
            acc[m] += pos[((m0 + m) % NN) * DD + t];
            g_h[(m0 + m) * DD + t] = acc[m];
            float v = acc[m];
#pragma unroll
            for (int o = 16; o; o >>= 1) v = fmaxf(v, __shfl_xor_sync(~0u, v, o));
            if (lane == 0) red[warp][m] = v;
        }
    }
    __syncthreads();
    if (t < 4)
        g_mx[m0 + t] = fmax3(fmaxf(red[0][t], red[1][t]), red[2][t], red[3][t]);
}

// ---------------------------------------------------------------
// qkv: {q,k,v} = trop_mm(h, W) - mx
// grid (196,3), block 256 (8 rows/block)
// ---------------------------------------------------------------
__global__ void __launch_bounds__(256) qkv_kernel(
        const float* __restrict__ qW, const float* __restrict__ kW,
        const float* __restrict__ vW) {
    extern __shared__ float dyn[];
    int t = threadIdx.x, m0 = blockIdx.x * 8;
    const float* W = (blockIdx.y == 0) ? qW : (blockIdx.y == 1) ? kW : vW;
    float* O = (blockIdx.y == 0) ? g_q : (blockIdx.y == 1) ? g_k : g_v;
    float acc[8];
    XRow xl{g_h, m0, DD};
    trop_core<8, DD>(xl, W, acc, dyn);
    combine<8>(acc, (float (*)[128])dyn);
    if (t < 128) {
#pragma unroll
        for (int m = 0; m < 8; m++)
            O[(m0 + m) * DD + t] = acc[m] - g_mx[m0 + m];
    }
}

// ---------------------------------------------------------------
// fused attention + residual + rowmax epilogue
// grid (25, 8), block 256 = 8 i-rows x 32 lanes (4 d each)
// ---------------------------------------------------------------
__global__ void attn_kernel() {
    __shared__ float ks[8][128];
    __shared__ float vs[8][128];
    int t = threadIdx.x;
    int b = blockIdx.y;
    int il = t >> 5, lane = t & 31;
    int d0 = lane * 4;
    int i = blockIdx.x * 8 + il;
    bool iv = (i < NN);

    const float* qp = g_q + (b * NN + (iv ? i : 0)) * DD + d0;
    float q0 = iv ? qp[0] : NEG, q1 = iv ? qp[1] : NEG;
    float q2 = iv ? qp[2] : NEG, q3 = iv ? qp[3] : NEG;
    unsigned long long Q01 = pk(q0, q1), Q23 = pk(q2, q3);
    float U0 = NEG, U1 = NEG, U2 = NEG, U3 = NEG;

    for (int j0 = 0; j0 < NN; j0 += 8) {
        int j = j0 + il;
        if (j < NN) {
            const float* kp_ = g_k + (b * NN + j) * DD + d0;
            const float* vp_ = g_v + (b * NN + j) * DD + d0;
            *(float4*)&ks[il][d0] = *(const float4*)&kp_[0];
            *(float4*)&vs[il][d0] = *(const float4*)&vp_[0];
        } else {
            float4 nv = make_float4(NEG, NEG, NEG, NEG);
            *(float4*)&ks[il][d0] = nv;
            *(float4*)&vs[il][d0] = nv;
        }
        __syncthreads();
#pragma unroll
        for (int jj = 0; jj < 8; jj++) {
            ulonglong2 kv = *(const ulonglong2*)&ks[jj][d0];
            float s0, s1, s2, s3;
            unpk(s0, s1, addx2(Q01, kv.x));
            unpk(s2, s3, addx2(Q23, kv.y));
            float s = fmaxf(fmax3(s0, s1, s2), s3);
#pragma unroll
            for (int o = 16; o; o >>= 1) s = fmaxf(s, __shfl_xor_sync(~0u, s, o));
            ulonglong2 vv = *(const ulonglong2*)&vs[jj][d0];
            unsigned long long S2 = pk(s, s);
            float a0, a1, a2, a3;
            unpk(a0, a1, addx2(S2, vv.x));
            unpk(a2, a3, addx2(S2, vv.y));
            U0 = fmaxf(U0, a0); U1 = fmaxf(U1, a1);
            U2 = fmaxf(U2, a2); U3 = fmaxf(U3, a3);
        }
        __syncthreads();
    }

    float um = fmax3(fmaxf(U0, U1), U2, U3);
#pragma unroll
    for (int o = 16; o; o >>= 1) um = fmaxf(um, __shfl_xor_sync(~0u, um, o));

    if (iv) {
        float* hp = g_h + (b * NN + i) * DD + d0;
        float h0 = fmaxf(hp[0], U0 - um), h1 = fmaxf(hp[1], U1 - um);
        float h2 = fmaxf(hp[2], U2 - um), h3 = fmaxf(hp[3], U3 - um);
        hp[0] = h0; hp[1] = h1; hp[2] = h2; hp[3] = h3;
        float v = fmax3(fmaxf(h0, h1), h2, h3);
#pragma unroll
        for (int o = 16; o; o >>= 1) v = fmaxf(v, __shfl_xor_sync(~0u, v, o));
        if (lane == 0) g_mx[b * NN + i] = v;
    }
}

// ---------------------------------------------------------------
// ff1: t = max(trop_mm(h, f1W) - mx, tau)
// grid (196, 2), block 256 (8 rows/block)
// ---------------------------------------------------------------
__global__ void __launch_bounds__(256) ff1_kernel(
        const float* __restrict__ W, const float* __restrict__ tau) {
    extern __shared__ float dyn[];
    int t = threadIdx.x, m0 = blockIdx.x * 8;
    float acc[8];
    XRow xl{g_h, m0, DD};
    trop_core<8, DD>(xl, W + blockIdx.y * 128 * DD, acc, dyn);
    combine<8>(acc, (float (*)[128])dyn);
    if (t < 128) {
        float tv = tau[0];
#pragma unroll
        for (int m = 0; m < 8; m++)
            g_t[(m0 + m) * DFF + blockIdx.y * 128 + t] =
                fmaxf(acc[m] - g_mx[m0 + m], tv);
    }
}

// ---------------------------------------------------------------
// ff2: u = trop_mm(t, f2W); h = max(h, u - rowmax(u)); g_mx = rowmax(h)
// grid 392, block 256 (4 rows/block)
// ---------------------------------------------------------------
__global__ void __launch_bounds__(256) ff2_kernel(const float* __restrict__ W) {
    extern __shared__ float dyn[];
    __shared__ float red[4][4];
    int t = threadIdx.x, m0 = blockIdx.x * 4;
    float acc[4];
    XRow xl{g_t, m0, DFF};
    trop_core<4, DFF>(xl, W, acc, dyn);
    combine<4>(acc, (float (*)[128])dyn);

    int warp = t >> 5, lane = t & 31;
    if (t < 128) {
#pragma unroll
        for (int m = 0; m < 4; m++) {
            float v = acc[m];
#pragma unroll
            for (int o = 16; o; o >>= 1) v = fmaxf(v, __shfl_xor_sync(~0u, v, o));
            if (lane == 0) red[warp][m] = v;
        }
    }
    __syncthreads();
    float hn[4];
    if (t < 128) {
#pragma unroll
        for (int m = 0; m < 4; m++) {
            float rm = fmax3(fmaxf(red[0][m], red[1][m]), red[2][m], red[3][m]);
            hn[m] = fmaxf(g_h[(m0 + m) * DD + t], acc[m] - rm);
            g_h[(m0 + m) * DD + t] = hn[m];
        }
    }
    __syncthreads();
    if (t < 128) {
#pragma unroll
        for (int m = 0; m < 4; m++) {
            float v = hn[m];
#pragma unroll
            for (int o = 16; o; o >>= 1) v = fmaxf(v, __shfl_xor_sync(~0u, v, o));
            if (lane == 0) red[warp][m] = v;
        }
    }
    __syncthreads();
    if (t < 4)
        g_mx[m0 + t] = fmax3(fmaxf(red[0][t], red[1][t]), red[2][t], red[3][t]);
}

// ---------------------------------------------------------------
// head with fused tropical global pool
// grid (8, 63), block 128 = 16 c-rows x 8 lanes (16 d each)
// ---------------------------------------------------------------
__global__ void head_kernel(const float* __restrict__ W, const float* __restrict__ ls,
                            float* __restrict__ out) {
    __shared__ float sp[128];
    int t = threadIdx.x, b = blockIdx.x;
    const float* hp = g_h + b * NN * DD + t;
    float v0 = NEG, v1 = NEG, v2 = NEG, v3 = NEG;
    for (int n = 0; n < NN; n += 4) {
        v0 = fmaxf(v0, hp[n * DD]);
        v1 = fmaxf(v1, hp[(n + 1) * DD]);
        v2 = fmaxf(v2, hp[(n + 2) * DD]);
        v3 = fmaxf(v3, hp[(n + 3) * DD]);
    }
    sp[t] = fmax3(fmaxf(v0, v1), v2, v3);
    __syncthreads();

    int c = blockIdx.y * 16 + (t >> 3);
    int dp = (t & 7) * 16;
    float acc = NEG;
    if (c < CC) {
        const float* w = W + c * DD + dp;
#pragma unroll
        for (int d = 0; d < 16; d += 4) {
            float4 wv = *(const float4*)&w[d];
            acc = fmax3(acc, fmaxf(sp[dp + d] + wv.x, sp[dp + d + 1] + wv.y),
                        fmaxf(sp[dp + d + 2] + wv.z, sp[dp + d + 3] + wv.w));
        }
    }
#pragma unroll
    for (int o = 4; o; o >>= 1) acc = fmaxf(acc, __shfl_xor_sync(~0u, acc, o));
    if ((t & 7) == 0 && c < CC) out[b * CC + c] = acc * ls[0];
}

// ---------------------------------------------------------------
extern "C" void kernel_launch(void* const* d_in, const int* in_sizes, int n_in,
                              void* d_out, int out_size) {
    const float* x      = (const float*)d_in[0];
    const float* embedW = (const float*)d_in[1];
    const float* pos    = (const float*)d_in[2];
    const float* qW[2]  = {(const float*)d_in[3],  (const float*)d_in[9]};
    const float* kW[2]  = {(const float*)d_in[4],  (const float*)d_in[10]};
    const float* vW[2]  = {(const float*)d_in[5],  (const float*)d_in[11]};
    const float* f1W[2] = {(const float*)d_in[6],  (const float*)d_in[12]};
    const float* f2W[2] = {(const float*)d_in[7],  (const float*)d_in[13]};
    const float* tau[2] = {(const float*)d_in[8],  (const float*)d_in[14]};
    const float* headW  = (const float*)d_in[15];
    const float* ls     = (const float*)d_in[16];
    float* out = (float*)d_out;

    cudaFuncSetAttribute(embed_kernel, cudaFuncAttributeMaxDynamicSharedMemorySize, SMEM4);
    cudaFuncSetAttribute(qkv_kernel,   cudaFuncAttributeMaxDynamicSharedMemorySize, SMEM8);
    cudaFuncSetAttribute(ff1_kernel,   cudaFuncAttributeMaxDynamicSharedMemorySize, SMEM8);
    cudaFuncSetAttribute(ff2_kernel,   cudaFuncAttributeMaxDynamicSharedMemorySize, SMEM4);

    embed_kernel<<<MM / 4, 256, SMEM4>>>(x, embedW, pos);

    for (int l = 0; l < 2; l++) {
        qkv_kernel<<<dim3(MM / 8, 3), 256, SMEM8>>>(qW[l], kW[l], vW[l]);
        attn_kernel<<<dim3(25, BB), 256>>>();
        ff1_kernel<<<dim3(MM / 8, 2), 256, SMEM8>>>(f1W[l], tau[l]);
        ff2_kernel<<<MM / 4, 256, SMEM4>>>(f2W[l]);
    }

    head_kernel<<<dim3(BB, 63), 128>>>(headW, ls, out);
}